// round 1
// baseline (speedup 1.0000x reference)
#include <cuda_runtime.h>
#include <math.h>

#define NMAX 100000
#define EMAX 3200000
#define D 128
#define KSTEPS 10
#define LVLS (KSTEPS + 1)

// ---- scratch (allocation-free rule: static __device__ arrays) ----
__device__ float g_H[(size_t)NMAX * LVLS * D];   // 563 MB: all propagation levels
__device__ int   g_indeg[NMAX];
__device__ int   g_outdeg[NMAX];
__device__ float g_dstn[NMAX];
__device__ float g_srcn[NMAX];
__device__ int   g_rowoff[NMAX + 1];
__device__ int   g_cursor[NMAX];
__device__ int   g_csr[EMAX];

__global__ void k_zero(int n) {
    int i = blockIdx.x * blockDim.x + threadIdx.x;
    if (i < n) { g_indeg[i] = 0; g_outdeg[i] = 0; g_cursor[i] = 0; }
}

__global__ void k_count(const int* __restrict__ src, const int* __restrict__ dst, int e) {
    int i = blockIdx.x * blockDim.x + threadIdx.x;
    if (i < e) {
        atomicAdd(&g_indeg[dst[i]], 1);
        atomicAdd(&g_outdeg[src[i]], 1);
    }
}

__global__ void k_norm(int n) {
    int i = blockIdx.x * blockDim.x + threadIdx.x;
    if (i < n) {
        g_dstn[i] = rsqrtf((float)max(g_indeg[i], 1));
        g_srcn[i] = rsqrtf((float)max(g_outdeg[i], 1));
    }
}

// feats -> level 0 of H
__global__ void k_copy(const float* __restrict__ feats, int n) {
    int i = blockIdx.x * blockDim.x + threadIdx.x;
    int tot = n * (D / 4);
    if (i < tot) {
        int node = i / (D / 4);
        int c    = i % (D / 4);
        reinterpret_cast<float4*>(g_H)[(size_t)node * LVLS * (D / 4) + c] =
            reinterpret_cast<const float4*>(feats)[i];
    }
}

// single-block exclusive scan of indeg -> rowoff (N=100K, trivial cost)
__global__ void k_scan(int n) {
    __shared__ int part[1024];
    int t = threadIdx.x;
    int chunk = (n + 1023) / 1024;
    int start = t * chunk;
    int end   = min(start + chunk, n);
    int s = 0;
    for (int i = start; i < end; i++) s += g_indeg[i];
    part[t] = s;
    __syncthreads();
    if (t == 0) {
        int acc = 0;
        for (int i = 0; i < 1024; i++) { int v = part[i]; part[i] = acc; acc += v; }
        g_rowoff[n] = acc;
    }
    __syncthreads();
    int acc = part[t];
    for (int i = start; i < end; i++) { g_rowoff[i] = acc; acc += g_indeg[i]; }
}

__global__ void k_fill(const int* __restrict__ src, const int* __restrict__ dst, int e) {
    int i = blockIdx.x * blockDim.x + threadIdx.x;
    if (i < e) {
        int v = dst[i];
        int p = atomicAdd(&g_cursor[v], 1);
        g_csr[g_rowoff[v] + p] = src[i];
    }
}

// pull-based SpMM: one warp per dst node, lane covers 4 of 128 dims (float4)
__global__ void k_spmm(int n, int k) {
    int gw   = (blockIdx.x * blockDim.x + threadIdx.x) >> 5;
    int lane = threadIdx.x & 31;
    if (gw >= n) return;
    int v   = gw;
    int beg = g_rowoff[v];
    int end = g_rowoff[v + 1];
    int km1 = k - 1;

    float4 acc = make_float4(0.f, 0.f, 0.f, 0.f);
    #pragma unroll 4
    for (int i = beg; i < end; i++) {
        int u = g_csr[i];                          // broadcast
        float w = g_srcn[u];                       // broadcast
        const float4* p =
            reinterpret_cast<const float4*>(g_H + ((size_t)u * LVLS + km1) * D) + lane;
        float4 x = *p;                             // coalesced 512B/row
        acc.x = fmaf(w, x.x, acc.x);
        acc.y = fmaf(w, x.y, acc.y);
        acc.z = fmaf(w, x.z, acc.z);
        acc.w = fmaf(w, x.w, acc.w);
    }
    float dn = g_dstn[v];
    float4 o = make_float4(acc.x * dn, acc.y * dn, acc.z * dn, acc.w * dn);
    *(reinterpret_cast<float4*>(g_H + ((size_t)v * LVLS + k) * D) + lane) = o;
}

// gated combination: one warp per node
__global__ void k_final(const float* __restrict__ s, float* __restrict__ out, int n) {
    int gw   = (blockIdx.x * blockDim.x + threadIdx.x) >> 5;
    int lane = threadIdx.x & 31;
    if (gw >= n) return;

    float4 sv = reinterpret_cast<const float4*>(s)[lane];
    const float4* hp = reinterpret_cast<const float4*>(g_H + (size_t)gw * LVLS * D) + lane;

    float4 acc = make_float4(0.f, 0.f, 0.f, 0.f);
    #pragma unroll
    for (int k = 0; k < LVLS; k++) {
        float4 h = hp[(size_t)k * (D / 4)];
        float pd = h.x * sv.x + h.y * sv.y + h.z * sv.z + h.w * sv.w;
        #pragma unroll
        for (int o = 16; o; o >>= 1) pd += __shfl_xor_sync(0xFFFFFFFFu, pd, o);
        float sg = 1.f / (1.f + expf(-pd));
        acc.x = fmaf(sg, h.x, acc.x);
        acc.y = fmaf(sg, h.y, acc.y);
        acc.z = fmaf(sg, h.z, acc.z);
        acc.w = fmaf(sg, h.w, acc.w);
    }
    reinterpret_cast<float4*>(out)[(size_t)gw * (D / 4) + lane] = acc;
}

extern "C" void kernel_launch(void* const* d_in, const int* in_sizes, int n_in,
                              void* d_out, int out_size) {
    const float* feats = (const float*)d_in[0];
    const float* s     = (const float*)d_in[1];
    const int*   src   = (const int*)d_in[2];
    const int*   dst   = (const int*)d_in[3];
    int n = in_sizes[0] / D;   // 100000
    int e = in_sizes[2];       // 3200000
    const int T = 256;

    k_zero <<<(n + T - 1) / T, T>>>(n);
    k_count<<<(e + T - 1) / T, T>>>(src, dst, e);
    k_norm <<<(n + T - 1) / T, T>>>(n);
    k_copy <<<(n * (D / 4) + T - 1) / T, T>>>(feats, n);
    k_scan <<<1, 1024>>>(n);
    k_fill <<<(e + T - 1) / T, T>>>(src, dst, e);

    int warps_grid = (n * 32 + T - 1) / T;
    for (int k = 1; k <= KSTEPS; k++)
        k_spmm<<<warps_grid, T>>>(n, k);

    k_final<<<warps_grid, T>>>(s, (float*)d_out, n);
}

// round 3
// speedup vs baseline: 1.3769x; 1.3769x over previous
#include <cuda_runtime.h>
#include <cuda_fp16.h>
#include <math.h>

#define NMAX 100000
#define EMAX 3200000
#define D 128
#define KSTEPS 10
#define LVLS (KSTEPS + 1)

// ---- scratch (allocation-free rule: static __device__ arrays) ----
__device__ float   g_H[(size_t)NMAX * LVLS * D];   // 563 MB: all propagation levels (fp32)
__device__ __half2 g_G[2][(size_t)NMAX * (D / 2)]; // 2 x 25.6 MB: pre-scaled fp16 gather buffers
__device__ int     g_indeg[NMAX];
__device__ int     g_outdeg[NMAX];
__device__ float   g_dstn[NMAX];
__device__ float   g_srcn[NMAX];
__device__ int     g_rowoff[NMAX + 1];
__device__ int     g_cursor[NMAX];
__device__ int     g_csr[EMAX];

__global__ void k_zero(int n) {
    int i = blockIdx.x * blockDim.x + threadIdx.x;
    if (i < n) { g_indeg[i] = 0; g_outdeg[i] = 0; g_cursor[i] = 0; }
}

__global__ void k_count(const int* __restrict__ src, const int* __restrict__ dst, int e) {
    int i = blockIdx.x * blockDim.x + threadIdx.x;
    if (i < e) {
        atomicAdd(&g_indeg[dst[i]], 1);
        atomicAdd(&g_outdeg[src[i]], 1);
    }
}

__global__ void k_norm(int n) {
    int i = blockIdx.x * blockDim.x + threadIdx.x;
    if (i < n) {
        g_dstn[i] = rsqrtf((float)max(g_indeg[i], 1));
        g_srcn[i] = rsqrtf((float)max(g_outdeg[i], 1));
    }
}

// feats -> H level 0 (fp32) and G[0] = feats * src_norm (fp16, pre-scaled)
__global__ void k_copy(const float* __restrict__ feats, int n) {
    int i = blockIdx.x * blockDim.x + threadIdx.x;
    int tot = n * (D / 4);
    if (i < tot) {
        int node = i / (D / 4);
        int c    = i % (D / 4);
        float4 v = reinterpret_cast<const float4*>(feats)[i];
        reinterpret_cast<float4*>(g_H)[(size_t)node * LVLS * (D / 4) + c] = v;
        float sn = g_srcn[node];
        __half2 p0 = __floats2half2_rn(v.x * sn, v.y * sn);
        __half2 p1 = __floats2half2_rn(v.z * sn, v.w * sn);
        uint2 ow;
        ow.x = *reinterpret_cast<unsigned int*>(&p0);
        ow.y = *reinterpret_cast<unsigned int*>(&p1);
        // node stride = 128 halfs = 32 uint2 = D/4  (bug was D/8)
        reinterpret_cast<uint2*>(g_G[0])[(size_t)node * (D / 4) + c] = ow;
    }
}

// single-block exclusive scan of indeg -> rowoff (N=100K, trivial cost)
__global__ void k_scan(int n) {
    __shared__ int part[1024];
    int t = threadIdx.x;
    int chunk = (n + 1023) / 1024;
    int start = t * chunk;
    int end   = min(start + chunk, n);
    int s = 0;
    for (int i = start; i < end; i++) s += g_indeg[i];
    part[t] = s;
    __syncthreads();
    if (t == 0) {
        int acc = 0;
        for (int i = 0; i < 1024; i++) { int v = part[i]; part[i] = acc; acc += v; }
        g_rowoff[n] = acc;
    }
    __syncthreads();
    int acc = part[t];
    for (int i = start; i < end; i++) { g_rowoff[i] = acc; acc += g_indeg[i]; }
}

__global__ void k_fill(const int* __restrict__ src, const int* __restrict__ dst, int e) {
    int i = blockIdx.x * blockDim.x + threadIdx.x;
    if (i < e) {
        int v = dst[i];
        int p = atomicAdd(&g_cursor[v], 1);
        g_csr[g_rowoff[v] + p] = src[i];
    }
}

// pull-based SpMM: one warp per dst node, lane covers 4 of 128 dims.
// Reads pre-scaled fp16 rows (256 B/edge), accumulates fp32, writes
// fp32 level into H and pre-scaled fp16 row into the next gather buffer.
__global__ void k_spmm(int n, int k, int cur) {
    int gw   = (blockIdx.x * blockDim.x + threadIdx.x) >> 5;
    int lane = threadIdx.x & 31;
    if (gw >= n) return;
    int beg = g_rowoff[gw];
    int end = g_rowoff[gw + 1];
    const __half2* __restrict__ G = g_G[cur];

    float ax = 0.f, ay = 0.f, az = 0.f, aw = 0.f;
    #pragma unroll 4
    for (int i = beg; i < end; i++) {
        int u = g_csr[i];                          // broadcast, L1-resident line
        uint2 raw = *reinterpret_cast<const uint2*>(G + (size_t)u * (D / 2) + 2 * lane);
        __half2 p0 = *reinterpret_cast<__half2*>(&raw.x);
        __half2 p1 = *reinterpret_cast<__half2*>(&raw.y);
        float2 f0 = __half22float2(p0);
        float2 f1 = __half22float2(p1);
        ax += f0.x; ay += f0.y; az += f1.x; aw += f1.y;
    }
    float dn = g_dstn[gw];
    float4 h = make_float4(ax * dn, ay * dn, az * dn, aw * dn);
    *(reinterpret_cast<float4*>(g_H + ((size_t)gw * LVLS + k) * D) + lane) = h;

    float sn = g_srcn[gw];
    __half2 o0 = __floats2half2_rn(h.x * sn, h.y * sn);
    __half2 o1 = __floats2half2_rn(h.z * sn, h.w * sn);
    uint2 ow;
    ow.x = *reinterpret_cast<unsigned int*>(&o0);
    ow.y = *reinterpret_cast<unsigned int*>(&o1);
    *reinterpret_cast<uint2*>(g_G[cur ^ 1] + (size_t)gw * (D / 2) + 2 * lane) = ow;
}

// gated combination: one warp per node, streams H (fp32) from DRAM
__global__ void k_final(const float* __restrict__ s, float* __restrict__ out, int n) {
    int gw   = (blockIdx.x * blockDim.x + threadIdx.x) >> 5;
    int lane = threadIdx.x & 31;
    if (gw >= n) return;

    float4 sv = reinterpret_cast<const float4*>(s)[lane];
    const float4* hp = reinterpret_cast<const float4*>(g_H + (size_t)gw * LVLS * D) + lane;

    float4 acc = make_float4(0.f, 0.f, 0.f, 0.f);
    #pragma unroll
    for (int k = 0; k < LVLS; k++) {
        float4 h = hp[(size_t)k * (D / 4)];
        float pd = h.x * sv.x + h.y * sv.y + h.z * sv.z + h.w * sv.w;
        #pragma unroll
        for (int o = 16; o; o >>= 1) pd += __shfl_xor_sync(0xFFFFFFFFu, pd, o);
        float sg = 1.f / (1.f + expf(-pd));
        acc.x = fmaf(sg, h.x, acc.x);
        acc.y = fmaf(sg, h.y, acc.y);
        acc.z = fmaf(sg, h.z, acc.z);
        acc.w = fmaf(sg, h.w, acc.w);
    }
    reinterpret_cast<float4*>(out)[(size_t)gw * (D / 4) + lane] = acc;
}

extern "C" void kernel_launch(void* const* d_in, const int* in_sizes, int n_in,
                              void* d_out, int out_size) {
    const float* feats = (const float*)d_in[0];
    const float* s     = (const float*)d_in[1];
    const int*   src   = (const int*)d_in[2];
    const int*   dst   = (const int*)d_in[3];
    int n = in_sizes[0] / D;   // 100000
    int e = in_sizes[2];       // 3200000
    const int T = 256;

    k_zero <<<(n + T - 1) / T, T>>>(n);
    k_count<<<(e + T - 1) / T, T>>>(src, dst, e);
    k_norm <<<(n + T - 1) / T, T>>>(n);
    k_copy <<<(n * (D / 4) + T - 1) / T, T>>>(feats, n);
    k_scan <<<1, 1024>>>(n);
    k_fill <<<(e + T - 1) / T, T>>>(src, dst, e);

    int warps_grid = (n * 32 + T - 1) / T;
    for (int k = 1; k <= KSTEPS; k++)
        k_spmm<<<warps_grid, T>>>(n, k, (k - 1) & 1);

    k_final<<<warps_grid, T>>>(s, (float*)d_out, n);
}

// round 4
// speedup vs baseline: 1.4440x; 1.0487x over previous
#include <cuda_runtime.h>
#include <cuda_fp16.h>
#include <math.h>

#define NMAX 100000
#define EMAX 3200000
#define D 128
#define KSTEPS 10

// ---- scratch (allocation-free rule: static __device__ arrays) ----
__device__ __half2 g_G[2][(size_t)NMAX * (D / 2)]; // 2 x 25.6 MB: pre-scaled fp16 gather buffers
__device__ int     g_indeg[NMAX];
__device__ int     g_outdeg[NMAX];
__device__ float   g_dstn[NMAX];
__device__ float   g_srcn[NMAX];
__device__ int     g_rowoff[NMAX + 1];
__device__ int     g_cursor[NMAX];
__device__ int     g_csr[EMAX];

__global__ void k_zero(int n) {
    int i = blockIdx.x * blockDim.x + threadIdx.x;
    if (i < n) { g_indeg[i] = 0; g_outdeg[i] = 0; g_cursor[i] = 0; }
}

__global__ void k_count(const int* __restrict__ src, const int* __restrict__ dst, int e) {
    int i = blockIdx.x * blockDim.x + threadIdx.x;
    if (i < e) {
        atomicAdd(&g_indeg[dst[i]], 1);
        atomicAdd(&g_outdeg[src[i]], 1);
    }
}

__global__ void k_norm(int n) {
    int i = blockIdx.x * blockDim.x + threadIdx.x;
    if (i < n) {
        g_dstn[i] = rsqrtf((float)max(g_indeg[i], 1));
        g_srcn[i] = rsqrtf((float)max(g_outdeg[i], 1));
    }
}

// warp per node: G[0] = feats * src_norm (fp16), out = sigmoid(feats.s)*feats (level-0 term)
__global__ void k_copy(const float* __restrict__ feats, const float* __restrict__ s,
                       float* __restrict__ out, int n) {
    int gw   = (blockIdx.x * blockDim.x + threadIdx.x) >> 5;
    int lane = threadIdx.x & 31;
    if (gw >= n) return;

    float4 v = reinterpret_cast<const float4*>(feats)[(size_t)gw * (D / 4) + lane];

    float sn = g_srcn[gw];
    __half2 p0 = __floats2half2_rn(v.x * sn, v.y * sn);
    __half2 p1 = __floats2half2_rn(v.z * sn, v.w * sn);
    uint2 ow;
    ow.x = *reinterpret_cast<unsigned int*>(&p0);
    ow.y = *reinterpret_cast<unsigned int*>(&p1);
    *reinterpret_cast<uint2*>(g_G[0] + (size_t)gw * (D / 2) + 2 * lane) = ow;

    float4 sv = reinterpret_cast<const float4*>(s)[lane];
    float pd = v.x * sv.x + v.y * sv.y + v.z * sv.z + v.w * sv.w;
    #pragma unroll
    for (int o = 16; o; o >>= 1) pd += __shfl_xor_sync(0xFFFFFFFFu, pd, o);
    float sg = 1.f / (1.f + expf(-pd));

    float4 ov = make_float4(sg * v.x, sg * v.y, sg * v.z, sg * v.w);
    reinterpret_cast<float4*>(out)[(size_t)gw * (D / 4) + lane] = ov;
}

// single-block exclusive scan of indeg -> rowoff (N=100K, trivial cost)
__global__ void k_scan(int n) {
    __shared__ int part[1024];
    int t = threadIdx.x;
    int chunk = (n + 1023) / 1024;
    int start = t * chunk;
    int end   = min(start + chunk, n);
    int s = 0;
    for (int i = start; i < end; i++) s += g_indeg[i];
    part[t] = s;
    __syncthreads();
    if (t == 0) {
        int acc = 0;
        for (int i = 0; i < 1024; i++) { int v = part[i]; part[i] = acc; acc += v; }
        g_rowoff[n] = acc;
    }
    __syncthreads();
    int acc = part[t];
    for (int i = start; i < end; i++) { g_rowoff[i] = acc; acc += g_indeg[i]; }
}

__global__ void k_fill(const int* __restrict__ src, const int* __restrict__ dst, int e) {
    int i = blockIdx.x * blockDim.x + threadIdx.x;
    if (i < e) {
        int v = dst[i];
        int p = atomicAdd(&g_cursor[v], 1);
        g_csr[g_rowoff[v] + p] = src[i];
    }
}

// fused pull-SpMM + gated epilogue: one warp per dst node.
// Gathers pre-scaled fp16 rows, forms level-k row h (fp32), adds
// sigmoid(h.s)*h into out, and writes pre-scaled fp16 row for next level.
__global__ void k_spmm(int n, int k, int cur,
                       const float* __restrict__ s, float* __restrict__ out) {
    int gw   = (blockIdx.x * blockDim.x + threadIdx.x) >> 5;
    int lane = threadIdx.x & 31;
    if (gw >= n) return;
    int beg = g_rowoff[gw];
    int end = g_rowoff[gw + 1];
    const __half2* __restrict__ G = g_G[cur];

    float ax = 0.f, ay = 0.f, az = 0.f, aw = 0.f;
    #pragma unroll 4
    for (int i = beg; i < end; i++) {
        int u = g_csr[i];                          // broadcast load
        uint2 raw = *reinterpret_cast<const uint2*>(G + (size_t)u * (D / 2) + 2 * lane);
        __half2 p0 = *reinterpret_cast<__half2*>(&raw.x);
        __half2 p1 = *reinterpret_cast<__half2*>(&raw.y);
        float2 f0 = __half22float2(p0);
        float2 f1 = __half22float2(p1);
        ax += f0.x; ay += f0.y; az += f1.x; aw += f1.y;
    }
    float dn = g_dstn[gw];
    float4 h = make_float4(ax * dn, ay * dn, az * dn, aw * dn);

    // gate = sigmoid(h . s), full 128-dim dot across the warp
    float4 sv = reinterpret_cast<const float4*>(s)[lane];
    float pd = h.x * sv.x + h.y * sv.y + h.z * sv.z + h.w * sv.w;
    #pragma unroll
    for (int o = 16; o; o >>= 1) pd += __shfl_xor_sync(0xFFFFFFFFu, pd, o);
    float sg = 1.f / (1.f + expf(-pd));

    // out += gate * h  (warp owns the row; deterministic)
    float4* op = reinterpret_cast<float4*>(out) + (size_t)gw * (D / 4) + lane;
    float4 o = *op;
    o.x = fmaf(sg, h.x, o.x);
    o.y = fmaf(sg, h.y, o.y);
    o.z = fmaf(sg, h.z, o.z);
    o.w = fmaf(sg, h.w, o.w);
    *op = o;

    // pre-scaled fp16 row for the next level (skip on last step)
    if (k < KSTEPS) {
        float sn = g_srcn[gw];
        __half2 o0 = __floats2half2_rn(h.x * sn, h.y * sn);
        __half2 o1 = __floats2half2_rn(h.z * sn, h.w * sn);
        uint2 ow;
        ow.x = *reinterpret_cast<unsigned int*>(&o0);
        ow.y = *reinterpret_cast<unsigned int*>(&o1);
        *reinterpret_cast<uint2*>(g_G[cur ^ 1] + (size_t)gw * (D / 2) + 2 * lane) = ow;
    }
}

extern "C" void kernel_launch(void* const* d_in, const int* in_sizes, int n_in,
                              void* d_out, int out_size) {
    const float* feats = (const float*)d_in[0];
    const float* s     = (const float*)d_in[1];
    const int*   src   = (const int*)d_in[2];
    const int*   dst   = (const int*)d_in[3];
    float* out = (float*)d_out;
    int n = in_sizes[0] / D;   // 100000
    int e = in_sizes[2];       // 3200000
    const int T = 256;

    k_zero <<<(n + T - 1) / T, T>>>(n);
    k_count<<<(e + T - 1) / T, T>>>(src, dst, e);
    k_norm <<<(n + T - 1) / T, T>>>(n);

    int warps_grid = (n * 32 + T - 1) / T;
    k_copy <<<warps_grid, T>>>(feats, s, out, n);
    k_scan <<<1, 1024>>>(n);
    k_fill <<<(e + T - 1) / T, T>>>(src, dst, e);

    for (int k = 1; k <= KSTEPS; k++)
        k_spmm<<<warps_grid, T>>>(n, k, (k - 1) & 1, s, out);
}

// round 5
// speedup vs baseline: 1.4580x; 1.0098x over previous
#include <cuda_runtime.h>
#include <cuda_fp16.h>
#include <math.h>

#define NMAX 100000
#define EMAX 3200000
#define D 128
#define KSTEPS 10
#define LVLS (KSTEPS + 1)

// ---- scratch (allocation-free rule: static __device__ arrays) ----
// All 11 propagation levels, pre-scaled by src_norm, fp16: G[k] = h_k * srcn
__device__ __half2 g_G[(size_t)LVLS * NMAX * (D / 2)];   // 282 MB
__device__ int     g_indeg[NMAX];
__device__ int     g_outdeg[NMAX];
__device__ float   g_dstn[NMAX];
__device__ float   g_srcn[NMAX];
__device__ float   g_srcn_inv[NMAX];
__device__ int     g_rowoff[NMAX + 1];
__device__ int     g_cursor[NMAX];
__device__ int     g_csr[EMAX];

__global__ void k_zero(int n) {
    int i = blockIdx.x * blockDim.x + threadIdx.x;
    if (i < n) { g_indeg[i] = 0; g_outdeg[i] = 0; g_cursor[i] = 0; }
}

__global__ void k_count(const int* __restrict__ src, const int* __restrict__ dst, int e) {
    int i = blockIdx.x * blockDim.x + threadIdx.x;
    if (i < e) {
        atomicAdd(&g_indeg[dst[i]], 1);
        atomicAdd(&g_outdeg[src[i]], 1);
    }
}

__global__ void k_norm(int n) {
    int i = blockIdx.x * blockDim.x + threadIdx.x;
    if (i < n) {
        g_dstn[i] = rsqrtf((float)max(g_indeg[i], 1));
        float sd  = sqrtf((float)max(g_outdeg[i], 1));
        g_srcn[i]     = 1.f / sd;   // rsqrt
        g_srcn_inv[i] = sd;         // exact reciprocal of srcn
    }
}

// warp per node: G[0] = feats * src_norm (fp16)
__global__ void k_copy(const float* __restrict__ feats, int n) {
    int gw   = (blockIdx.x * blockDim.x + threadIdx.x) >> 5;
    int lane = threadIdx.x & 31;
    if (gw >= n) return;

    float4 v = reinterpret_cast<const float4*>(feats)[(size_t)gw * (D / 4) + lane];
    float sn = g_srcn[gw];
    __half2 p0 = __floats2half2_rn(v.x * sn, v.y * sn);
    __half2 p1 = __floats2half2_rn(v.z * sn, v.w * sn);
    uint2 ow;
    ow.x = *reinterpret_cast<unsigned int*>(&p0);
    ow.y = *reinterpret_cast<unsigned int*>(&p1);
    *reinterpret_cast<uint2*>(g_G + (size_t)gw * (D / 2) + 2 * lane) = ow;
}

// single-block exclusive scan of indeg -> rowoff (N=100K, trivial cost)
__global__ void k_scan(int n) {
    __shared__ int part[1024];
    int t = threadIdx.x;
    int chunk = (n + 1023) / 1024;
    int start = t * chunk;
    int end   = min(start + chunk, n);
    int s = 0;
    for (int i = start; i < end; i++) s += g_indeg[i];
    part[t] = s;
    __syncthreads();
    if (t == 0) {
        int acc = 0;
        for (int i = 0; i < 1024; i++) { int v = part[i]; part[i] = acc; acc += v; }
        g_rowoff[n] = acc;
    }
    __syncthreads();
    int acc = part[t];
    for (int i = start; i < end; i++) { g_rowoff[i] = acc; acc += g_indeg[i]; }
}

__global__ void k_fill(const int* __restrict__ src, const int* __restrict__ dst, int e) {
    int i = blockIdx.x * blockDim.x + threadIdx.x;
    if (i < e) {
        int v = dst[i];
        int p = atomicAdd(&g_cursor[v], 1);
        g_csr[g_rowoff[v] + p] = src[i];
    }
}

// pull-based SpMM: one warp per dst node, lane covers 4 of 128 dims.
// Reads pre-scaled fp16 rows of level k-1, accumulates fp32, writes
// pre-scaled fp16 row of level k. No epilogue traffic.
__global__ void k_spmm(int n, int k) {
    int gw   = (blockIdx.x * blockDim.x + threadIdx.x) >> 5;
    int lane = threadIdx.x & 31;
    if (gw >= n) return;
    int beg = g_rowoff[gw];
    int end = g_rowoff[gw + 1];
    const __half2* __restrict__ Gin = g_G + (size_t)(k - 1) * NMAX * (D / 2);

    float ax = 0.f, ay = 0.f, az = 0.f, aw = 0.f;
    #pragma unroll 4
    for (int i = beg; i < end; i++) {
        int u = g_csr[i];                          // broadcast load
        uint2 raw = *reinterpret_cast<const uint2*>(Gin + (size_t)u * (D / 2) + 2 * lane);
        __half2 p0 = *reinterpret_cast<__half2*>(&raw.x);
        __half2 p1 = *reinterpret_cast<__half2*>(&raw.y);
        float2 f0 = __half22float2(p0);
        float2 f1 = __half22float2(p1);
        ax += f0.x; ay += f0.y; az += f1.x; aw += f1.y;
    }
    // h_k = acc * dstn ; store pre-scaled for next gather: G[k] = h_k * srcn
    float w = g_dstn[gw] * g_srcn[gw];
    __half2 o0 = __floats2half2_rn(ax * w, ay * w);
    __half2 o1 = __floats2half2_rn(az * w, aw * w);
    uint2 ow;
    ow.x = *reinterpret_cast<unsigned int*>(&o0);
    ow.y = *reinterpret_cast<unsigned int*>(&o1);
    *reinterpret_cast<uint2*>(g_G + ((size_t)k * NMAX + gw) * (D / 2) + 2 * lane) = ow;
}

// gated combination from the 11 fp16 level buffers: one warp per node.
// h_k = inv * g_k  (inv = 1/srcn, constant per node) =>
//   pd_k = inv * (g_k . s) ;  out = inv * sum_k sigmoid(pd_k) * g_k
__global__ void k_final(const float* __restrict__ s, float* __restrict__ out, int n) {
    int gw   = (blockIdx.x * blockDim.x + threadIdx.x) >> 5;
    int lane = threadIdx.x & 31;
    if (gw >= n) return;

    float4 sv = reinterpret_cast<const float4*>(s)[lane];
    float inv = g_srcn_inv[gw];
    size_t base = (size_t)gw * (D / 2) + 2 * lane;

    float ax = 0.f, ay = 0.f, az = 0.f, aw = 0.f;
    #pragma unroll
    for (int k = 0; k < LVLS; k++) {
        uint2 raw = *reinterpret_cast<const uint2*>(g_G + (size_t)k * NMAX * (D / 2) + base);
        __half2 p0 = *reinterpret_cast<__half2*>(&raw.x);
        __half2 p1 = *reinterpret_cast<__half2*>(&raw.y);
        float2 f0 = __half22float2(p0);
        float2 f1 = __half22float2(p1);

        float pd = f0.x * sv.x + f0.y * sv.y + f1.x * sv.z + f1.y * sv.w;
        #pragma unroll
        for (int o = 16; o; o >>= 1) pd += __shfl_xor_sync(0xFFFFFFFFu, pd, o);
        float sg = 1.f / (1.f + expf(-pd * inv));

        ax = fmaf(sg, f0.x, ax);
        ay = fmaf(sg, f0.y, ay);
        az = fmaf(sg, f1.x, az);
        aw = fmaf(sg, f1.y, aw);
    }
    float4 o = make_float4(ax * inv, ay * inv, az * inv, aw * inv);
    reinterpret_cast<float4*>(out)[(size_t)gw * (D / 4) + lane] = o;
}

extern "C" void kernel_launch(void* const* d_in, const int* in_sizes, int n_in,
                              void* d_out, int out_size) {
    const float* feats = (const float*)d_in[0];
    const float* s     = (const float*)d_in[1];
    const int*   src   = (const int*)d_in[2];
    const int*   dst   = (const int*)d_in[3];
    float* out = (float*)d_out;
    int n = in_sizes[0] / D;   // 100000
    int e = in_sizes[2];       // 3200000
    const int T = 256;

    k_zero <<<(n + T - 1) / T, T>>>(n);
    k_count<<<(e + T - 1) / T, T>>>(src, dst, e);
    k_norm <<<(n + T - 1) / T, T>>>(n);

    int warps_grid = (n * 32 + T - 1) / T;
    k_copy <<<warps_grid, T>>>(feats, n);
    k_scan <<<1, 1024>>>(n);
    k_fill <<<(e + T - 1) / T, T>>>(src, dst, e);

    for (int k = 1; k <= KSTEPS; k++)
        k_spmm<<<warps_grid, T>>>(n, k);

    k_final<<<warps_grid, T>>>(s, out, n);
}

// round 6
// speedup vs baseline: 1.4946x; 1.0251x over previous
#include <cuda_runtime.h>
#include <cuda_fp16.h>
#include <math.h>

#define NMAX 100000
#define EMAX 3200000
#define D 128
#define KSTEPS 10
#define LVLS (KSTEPS + 1)

// ---- scratch (allocation-free rule: static __device__ arrays) ----
// All 11 propagation levels, pre-scaled by src_norm, fp16: G[k] = h_k * srcn
__device__ __half2 g_G[(size_t)LVLS * NMAX * (D / 2)];   // 282 MB
__device__ int     g_indeg[NMAX];
__device__ int     g_outdeg[NMAX];
__device__ float   g_w[NMAX];        // dstn * srcn (spmm output scale)
__device__ float   g_srcn[NMAX];
__device__ float   g_srcn_inv[NMAX];
__device__ int     g_rowoff[NMAX + 1];
__device__ int     g_cursor[NMAX];
__device__ int     g_csr[EMAX];

__global__ void k_zero(int n) {
    int i = blockIdx.x * blockDim.x + threadIdx.x;
    if (i < n) { g_indeg[i] = 0; g_outdeg[i] = 0; g_cursor[i] = 0; }
}

__global__ void k_count(const int* __restrict__ src, const int* __restrict__ dst, int e) {
    int i = blockIdx.x * blockDim.x + threadIdx.x;
    if (i < e) {
        atomicAdd(&g_indeg[dst[i]], 1);
        atomicAdd(&g_outdeg[src[i]], 1);
    }
}

__global__ void k_norm(int n) {
    int i = blockIdx.x * blockDim.x + threadIdx.x;
    if (i < n) {
        float dn = rsqrtf((float)max(g_indeg[i], 1));
        float sd = sqrtf((float)max(g_outdeg[i], 1));
        float sn = 1.f / sd;
        g_srcn[i]     = sn;
        g_srcn_inv[i] = sd;
        g_w[i]        = dn * sn;
    }
}

// warp per node: G[0] = feats * src_norm (fp16)
__global__ void k_copy(const float* __restrict__ feats, int n) {
    int gw   = (blockIdx.x * blockDim.x + threadIdx.x) >> 5;
    int lane = threadIdx.x & 31;
    if (gw >= n) return;

    float4 v = reinterpret_cast<const float4*>(feats)[(size_t)gw * (D / 4) + lane];
    float sn = g_srcn[gw];
    __half2 p0 = __floats2half2_rn(v.x * sn, v.y * sn);
    __half2 p1 = __floats2half2_rn(v.z * sn, v.w * sn);
    uint2 ow;
    ow.x = *reinterpret_cast<unsigned int*>(&p0);
    ow.y = *reinterpret_cast<unsigned int*>(&p1);
    *reinterpret_cast<uint2*>(g_G + (size_t)gw * (D / 2) + 2 * lane) = ow;
}

// single-block exclusive scan of indeg -> rowoff (N=100K, trivial cost)
__global__ void k_scan(int n) {
    __shared__ int part[1024];
    int t = threadIdx.x;
    int chunk = (n + 1023) / 1024;
    int start = t * chunk;
    int end   = min(start + chunk, n);
    int s = 0;
    for (int i = start; i < end; i++) s += g_indeg[i];
    part[t] = s;
    __syncthreads();
    if (t == 0) {
        int acc = 0;
        for (int i = 0; i < 1024; i++) { int v = part[i]; part[i] = acc; acc += v; }
        g_rowoff[n] = acc;
    }
    __syncthreads();
    int acc = part[t];
    for (int i = start; i < end; i++) { g_rowoff[i] = acc; acc += g_indeg[i]; }
}

__global__ void k_fill(const int* __restrict__ src, const int* __restrict__ dst, int e) {
    int i = blockIdx.x * blockDim.x + threadIdx.x;
    if (i < e) {
        int v = dst[i];
        int p = atomicAdd(&g_cursor[v], 1);
        g_csr[g_rowoff[v] + p] = src[i];
    }
}

// pull-based SpMM: one warp per dst node, lane covers 4 of 128 dims.
// csr indices are loaded coalesced in chunks of 32 (one load per lane),
// broadcast per edge via shfl -> inner loop is 32 INDEPENDENT gathers
// (no per-edge L2-latency index load in the address chain).
__global__ void k_spmm(int n, int k) {
    int gw   = (blockIdx.x * blockDim.x + threadIdx.x) >> 5;
    int lane = threadIdx.x & 31;
    if (gw >= n) return;
    int beg = g_rowoff[gw];
    int end = g_rowoff[gw + 1];
    const __half2* __restrict__ Gin = g_G + (size_t)(k - 1) * NMAX * (D / 2);

    float ax = 0.f, ay = 0.f, az = 0.f, aw = 0.f;

    int i = beg;
    for (; i + 32 <= end; i += 32) {
        int idx = g_csr[i + lane];                 // coalesced, 1 load / 32 edges
        #pragma unroll 8
        for (int j = 0; j < 32; j++) {
            int u = __shfl_sync(0xFFFFFFFFu, idx, j);
            uint2 raw = *reinterpret_cast<const uint2*>(Gin + (size_t)u * (D / 2) + 2 * lane);
            __half2 p0 = *reinterpret_cast<__half2*>(&raw.x);
            __half2 p1 = *reinterpret_cast<__half2*>(&raw.y);
            float2 f0 = __half22float2(p0);
            float2 f1 = __half22float2(p1);
            ax += f0.x; ay += f0.y; az += f1.x; aw += f1.y;
        }
    }
    // remainder (< 32 edges)
    int m = end - i;
    if (m > 0) {
        int idx = (lane < m) ? g_csr[i + lane] : 0;
        for (int j = 0; j < m; j++) {
            int u = __shfl_sync(0xFFFFFFFFu, idx, j);
            uint2 raw = *reinterpret_cast<const uint2*>(Gin + (size_t)u * (D / 2) + 2 * lane);
            __half2 p0 = *reinterpret_cast<__half2*>(&raw.x);
            __half2 p1 = *reinterpret_cast<__half2*>(&raw.y);
            float2 f0 = __half22float2(p0);
            float2 f1 = __half22float2(p1);
            ax += f0.x; ay += f0.y; az += f1.x; aw += f1.y;
        }
    }

    // G[k] = (acc * dstn) * srcn, stored fp16 pre-scaled for next gather
    float w = g_w[gw];
    __half2 o0 = __floats2half2_rn(ax * w, ay * w);
    __half2 o1 = __floats2half2_rn(az * w, aw * w);
    uint2 ow;
    ow.x = *reinterpret_cast<unsigned int*>(&o0);
    ow.y = *reinterpret_cast<unsigned int*>(&o1);
    *reinterpret_cast<uint2*>(g_G + ((size_t)k * NMAX + gw) * (D / 2) + 2 * lane) = ow;
}

// gated combination from the 11 fp16 level buffers: one warp per node.
// h_k = inv * g_k  (inv = 1/srcn) =>
//   pd_k = inv * (g_k . s) ;  out = inv * sum_k sigmoid(pd_k) * g_k
__global__ void k_final(const float* __restrict__ s, float* __restrict__ out, int n) {
    int gw   = (blockIdx.x * blockDim.x + threadIdx.x) >> 5;
    int lane = threadIdx.x & 31;
    if (gw >= n) return;

    float4 sv = reinterpret_cast<const float4*>(s)[lane];
    float inv = g_srcn_inv[gw];
    size_t base = (size_t)gw * (D / 2) + 2 * lane;

    float ax = 0.f, ay = 0.f, az = 0.f, aw = 0.f;
    #pragma unroll
    for (int k = 0; k < LVLS; k++) {
        uint2 raw = *reinterpret_cast<const uint2*>(g_G + (size_t)k * NMAX * (D / 2) + base);
        __half2 p0 = *reinterpret_cast<__half2*>(&raw.x);
        __half2 p1 = *reinterpret_cast<__half2*>(&raw.y);
        float2 f0 = __half22float2(p0);
        float2 f1 = __half22float2(p1);

        float pd = f0.x * sv.x + f0.y * sv.y + f1.x * sv.z + f1.y * sv.w;
        #pragma unroll
        for (int o = 16; o; o >>= 1) pd += __shfl_xor_sync(0xFFFFFFFFu, pd, o);
        float sg = 1.f / (1.f + expf(-pd * inv));

        ax = fmaf(sg, f0.x, ax);
        ay = fmaf(sg, f0.y, ay);
        az = fmaf(sg, f1.x, az);
        aw = fmaf(sg, f1.y, aw);
    }
    float4 o = make_float4(ax * inv, ay * inv, az * inv, aw * inv);
    reinterpret_cast<float4*>(out)[(size_t)gw * (D / 4) + lane] = o;
}

extern "C" void kernel_launch(void* const* d_in, const int* in_sizes, int n_in,
                              void* d_out, int out_size) {
    const float* feats = (const float*)d_in[0];
    const float* s     = (const float*)d_in[1];
    const int*   src   = (const int*)d_in[2];
    const int*   dst   = (const int*)d_in[3];
    float* out = (float*)d_out;
    int n = in_sizes[0] / D;   // 100000
    int e = in_sizes[2];       // 3200000
    const int T = 256;

    k_zero <<<(n + T - 1) / T, T>>>(n);
    k_count<<<(e + T - 1) / T, T>>>(src, dst, e);
    k_norm <<<(n + T - 1) / T, T>>>(n);

    int warps_grid = (n * 32 + T - 1) / T;
    k_copy <<<warps_grid, T>>>(feats, n);
    k_scan <<<1, 1024>>>(n);
    k_fill <<<(e + T - 1) / T, T>>>(src, dst, e);

    for (int k = 1; k <= KSTEPS; k++)
        k_spmm<<<warps_grid, T>>>(n, k);

    k_final<<<warps_grid, T>>>(s, out, n);
}

// round 7
// speedup vs baseline: 1.5642x; 1.0466x over previous
#include <cuda_runtime.h>
#include <cuda_fp16.h>
#include <math.h>

#define NMAX 100000
#define EMAX 3200000
#define D 128
#define KSTEPS 10
#define LVLS (KSTEPS + 1)

// ---- scratch (allocation-free rule: static __device__ arrays) ----
// All 11 propagation levels, pre-scaled by src_norm, fp16: G[k] = h_k * srcn
__device__ __half2 g_G[(size_t)LVLS * NMAX * (D / 2)];   // 282 MB
__device__ int     g_indeg[NMAX];
__device__ int     g_outdeg[NMAX];
__device__ float   g_w[NMAX];        // dstn * srcn (spmm output scale)
__device__ float   g_srcn[NMAX];
__device__ float   g_srcn_inv[NMAX];
__device__ int     g_rowoff[NMAX + 1];
__device__ int     g_cursor[NMAX];
__device__ int     g_csr[EMAX];

__global__ void k_zero(int n) {
    int i = blockIdx.x * blockDim.x + threadIdx.x;
    if (i < n) { g_indeg[i] = 0; g_outdeg[i] = 0; g_cursor[i] = 0; }
}

__global__ void k_count(const int* __restrict__ src, const int* __restrict__ dst, int e) {
    int i = blockIdx.x * blockDim.x + threadIdx.x;
    if (i < e) {
        atomicAdd(&g_indeg[dst[i]], 1);
        atomicAdd(&g_outdeg[src[i]], 1);
    }
}

__global__ void k_norm(int n) {
    int i = blockIdx.x * blockDim.x + threadIdx.x;
    if (i < n) {
        float dn = rsqrtf((float)max(g_indeg[i], 1));
        float sd = sqrtf((float)max(g_outdeg[i], 1));
        float sn = 1.f / sd;
        g_srcn[i]     = sn;
        g_srcn_inv[i] = sd;
        g_w[i]        = dn * sn;
    }
}

// warp per node: G[0] = feats * src_norm (fp16)
__global__ void k_copy(const float* __restrict__ feats, int n) {
    int gw   = (blockIdx.x * blockDim.x + threadIdx.x) >> 5;
    int lane = threadIdx.x & 31;
    if (gw >= n) return;

    float4 v = reinterpret_cast<const float4*>(feats)[(size_t)gw * (D / 4) + lane];
    float sn = g_srcn[gw];
    __half2 p0 = __floats2half2_rn(v.x * sn, v.y * sn);
    __half2 p1 = __floats2half2_rn(v.z * sn, v.w * sn);
    uint2 ow;
    ow.x = *reinterpret_cast<unsigned int*>(&p0);
    ow.y = *reinterpret_cast<unsigned int*>(&p1);
    *reinterpret_cast<uint2*>(g_G + (size_t)gw * (D / 2) + 2 * lane) = ow;
}

// single-block exclusive scan of indeg -> rowoff (N=100K, trivial cost)
__global__ void k_scan(int n) {
    __shared__ int part[1024];
    int t = threadIdx.x;
    int chunk = (n + 1023) / 1024;
    int start = t * chunk;
    int end   = min(start + chunk, n);
    int s = 0;
    for (int i = start; i < end; i++) s += g_indeg[i];
    part[t] = s;
    __syncthreads();
    if (t == 0) {
        int acc = 0;
        for (int i = 0; i < 1024; i++) { int v = part[i]; part[i] = acc; acc += v; }
        g_rowoff[n] = acc;
    }
    __syncthreads();
    int acc = part[t];
    for (int i = start; i < end; i++) { g_rowoff[i] = acc; acc += g_indeg[i]; }
}

__global__ void k_fill(const int* __restrict__ src, const int* __restrict__ dst, int e) {
    int i = blockIdx.x * blockDim.x + threadIdx.x;
    if (i < e) {
        int v = dst[i];
        int p = atomicAdd(&g_cursor[v], 1);
        g_csr[g_rowoff[v] + p] = src[i];
    }
}

__device__ __forceinline__ void acc8(uint4 raw, float* a) {
    __half2 h0 = *reinterpret_cast<__half2*>(&raw.x);
    __half2 h1 = *reinterpret_cast<__half2*>(&raw.y);
    __half2 h2 = *reinterpret_cast<__half2*>(&raw.z);
    __half2 h3 = *reinterpret_cast<__half2*>(&raw.w);
    float2 f0 = __half22float2(h0);
    float2 f1 = __half22float2(h1);
    float2 f2 = __half22float2(h2);
    float2 f3 = __half22float2(h3);
    a[0] += f0.x; a[1] += f0.y; a[2] += f1.x; a[3] += f1.y;
    a[4] += f2.x; a[5] += f2.y; a[6] += f3.x; a[7] += f3.y;
}

// pull-based SpMM: one warp per dst node, TWO edges per warp-iteration.
// Half-warp h (lanes 0-15 / 16-31) covers the full 256B row of its edge via
// uint4 (16B/lane). csr chunk is loaded coalesced and broadcast via shfl.
// End: fold the two half-warps with shfl_xor(16).
__global__ void k_spmm(int n, int k) {
    int gw   = (blockIdx.x * blockDim.x + threadIdx.x) >> 5;
    int lane = threadIdx.x & 31;
    if (gw >= n) return;
    int beg = g_rowoff[gw];
    int end = g_rowoff[gw + 1];
    const uint4* __restrict__ Gin =
        reinterpret_cast<const uint4*>(g_G + (size_t)(k - 1) * NMAX * (D / 2));
    int h    = lane & 15;   // position within half-warp: 16B slot of the row
    int half = lane >> 4;   // which edge of the pair this lane serves

    float a[8];
    #pragma unroll
    for (int d = 0; d < 8; d++) a[d] = 0.f;

    int i = beg;
    for (; i + 32 <= end; i += 32) {
        int idx = g_csr[i + lane];                 // coalesced, 1 load / 32 edges
        #pragma unroll 8
        for (int j = 0; j < 16; j++) {
            int u = __shfl_sync(0xFFFFFFFFu, idx, 2 * j + half);
            acc8(Gin[(size_t)u * 16 + h], a);
        }
    }
    int m = end - i;
    if (m > 0) {
        int idx = (lane < m) ? g_csr[i + lane] : 0;
        int j = 0;
        for (; j + 2 <= m; j += 2) {
            int u = __shfl_sync(0xFFFFFFFFu, idx, j + half);
            acc8(Gin[(size_t)u * 16 + h], a);
        }
        if (j < m) {
            int u = __shfl_sync(0xFFFFFFFFu, idx, j);
            if (half == 0) acc8(Gin[(size_t)u * 16 + h], a);
        }
    }

    // fold edge-A / edge-B partials
    #pragma unroll
    for (int d = 0; d < 8; d++) a[d] += __shfl_xor_sync(0xFFFFFFFFu, a[d], 16);

    // G[k] = (acc * dstn) * srcn, stored fp16 pre-scaled for next gather
    float w = g_w[gw];
    if (lane < 16) {
        __half2 o0 = __floats2half2_rn(a[0] * w, a[1] * w);
        __half2 o1 = __floats2half2_rn(a[2] * w, a[3] * w);
        __half2 o2 = __floats2half2_rn(a[4] * w, a[5] * w);
        __half2 o3 = __floats2half2_rn(a[6] * w, a[7] * w);
        uint4 ow;
        ow.x = *reinterpret_cast<unsigned int*>(&o0);
        ow.y = *reinterpret_cast<unsigned int*>(&o1);
        ow.z = *reinterpret_cast<unsigned int*>(&o2);
        ow.w = *reinterpret_cast<unsigned int*>(&o3);
        reinterpret_cast<uint4*>(g_G + ((size_t)k * NMAX + gw) * (D / 2))[h] = ow;
    }
}

// gated combination from the 11 fp16 level buffers: one warp per node.
// h_k = inv * g_k  (inv = 1/srcn) =>
//   pd_k = inv * (g_k . s) ;  out = inv * sum_k sigmoid(pd_k) * g_k
__global__ void k_final(const float* __restrict__ s, float* __restrict__ out, int n) {
    int gw   = (blockIdx.x * blockDim.x + threadIdx.x) >> 5;
    int lane = threadIdx.x & 31;
    if (gw >= n) return;

    float4 sv = reinterpret_cast<const float4*>(s)[lane];
    float inv = g_srcn_inv[gw];
    size_t base = (size_t)gw * (D / 2) + 2 * lane;

    float ax = 0.f, ay = 0.f, az = 0.f, aw = 0.f;
    #pragma unroll
    for (int k = 0; k < LVLS; k++) {
        uint2 raw = *reinterpret_cast<const uint2*>(g_G + (size_t)k * NMAX * (D / 2) + base);
        __half2 p0 = *reinterpret_cast<__half2*>(&raw.x);
        __half2 p1 = *reinterpret_cast<__half2*>(&raw.y);
        float2 f0 = __half22float2(p0);
        float2 f1 = __half22float2(p1);

        float pd = f0.x * sv.x + f0.y * sv.y + f1.x * sv.z + f1.y * sv.w;
        #pragma unroll
        for (int o = 16; o; o >>= 1) pd += __shfl_xor_sync(0xFFFFFFFFu, pd, o);
        float sg = 1.f / (1.f + expf(-pd * inv));

        ax = fmaf(sg, f0.x, ax);
        ay = fmaf(sg, f0.y, ay);
        az = fmaf(sg, f1.x, az);
        aw = fmaf(sg, f1.y, aw);
    }
    float4 o = make_float4(ax * inv, ay * inv, az * inv, aw * inv);
    reinterpret_cast<float4*>(out)[(size_t)gw * (D / 4) + lane] = o;
}

extern "C" void kernel_launch(void* const* d_in, const int* in_sizes, int n_in,
                              void* d_out, int out_size) {
    const float* feats = (const float*)d_in[0];
    const float* s     = (const float*)d_in[1];
    const int*   src   = (const int*)d_in[2];
    const int*   dst   = (const int*)d_in[3];
    float* out = (float*)d_out;
    int n = in_sizes[0] / D;   // 100000
    int e = in_sizes[2];       // 3200000
    const int T = 256;

    k_zero <<<(n + T - 1) / T, T>>>(n);
    k_count<<<(e + T - 1) / T, T>>>(src, dst, e);
    k_norm <<<(n + T - 1) / T, T>>>(n);

    int warps_grid = (n * 32 + T - 1) / T;
    k_copy <<<warps_grid, T>>>(feats, n);
    k_scan <<<1, 1024>>>(n);
    k_fill <<<(e + T - 1) / T, T>>>(src, dst, e);

    for (int k = 1; k <= KSTEPS; k++)
        k_spmm<<<warps_grid, T>>>(n, k);

    k_final<<<warps_grid, T>>>(s, out, n);
}